// round 1
// baseline (speedup 1.0000x reference)
#include <cuda_runtime.h>
#include <cstdint>

// high_order_input: x[4,8,128,128] f32 -> out[4,8,210,16384] f32
// ht2: all 45 pairs col_i*col_j (i<=j), ht3: all 165 triples col_i*col_j*col_k (i<=j<=k),
// concatenated. Index tensors tpcm2/tpcm3 are compile-time fixed for K=3 and are
// reproduced here by loop enumeration order (verified against reference construction).

#define HWDIM 128
#define LPIX  (HWDIM * HWDIM)   // 16384
#define NTERM 210

__global__ __launch_bounds__(256, 4)
void high_order_kernel(const float* __restrict__ x, float* __restrict__ out)
{
    const int tid = blockIdx.x * blockDim.x + threadIdx.x;
    // 32 planes * 16384 pixels / 4 pixels-per-thread = 131072 threads
    const int plane = tid >> 12;          // tid / 4096
    const int q     = tid & 4095;
    const int h     = q >> 5;             // q / 32
    const int w0    = (q & 31) << 2;      // 4-pixel group start

    const float* __restrict__ xp = x + (size_t)plane * LPIX;

    // Gather 3x3 neighborhood for 4 consecutive pixels: col[kh*3+kw] is a float4
    // holding x[h+kh-1][w0+kw-1 .. w0+kw+2] with zero padding.
    float4 col[9];
    #pragma unroll
    for (int dr = 0; dr < 3; dr++) {
        const int r = h + dr - 1;
        float v0, v5;
        float4 mid;
        if (r < 0 || r >= HWDIM) {
            v0 = 0.f; v5 = 0.f;
            mid = make_float4(0.f, 0.f, 0.f, 0.f);
        } else {
            const float* rp = xp + r * HWDIM + w0;
            mid = *reinterpret_cast<const float4*>(rp);          // aligned (w0 % 4 == 0)
            v0 = (w0 > 0)          ? __ldg(rp - 1) : 0.f;
            v5 = (w0 + 4 < HWDIM)  ? __ldg(rp + 4) : 0.f;
        }
        col[dr * 3 + 0] = make_float4(v0,    mid.x, mid.y, mid.z);
        col[dr * 3 + 1] = mid;
        col[dr * 3 + 2] = make_float4(mid.y, mid.z, mid.w, v5);
    }

    // Output base for this thread's 4 pixels.
    float* __restrict__ obase = out + (size_t)plane * NTERM * LPIX + (size_t)(h * HWDIM + w0);

    // Order-2 slots t = 0..44 in (i-major, j>=i) order; order-3 slots t = 45..209
    // in (i-major, j>=i, k>=j) order. p_ij is both the ht2 value and the shared
    // prefix of all ht3 triples (i,j,*).
    int t2 = 0;
    int t3 = 45;
    #pragma unroll
    for (int i = 0; i < 9; i++) {
        #pragma unroll
        for (int j = i; j < 9; j++) {
            float4 p;
            p.x = col[i].x * col[j].x;
            p.y = col[i].y * col[j].y;
            p.z = col[i].z * col[j].z;
            p.w = col[i].w * col[j].w;
            __stcs(reinterpret_cast<float4*>(obase + (size_t)t2 * LPIX), p);
            t2++;
            #pragma unroll
            for (int k = j; k < 9; k++) {
                float4 r;
                r.x = p.x * col[k].x;
                r.y = p.y * col[k].y;
                r.z = p.z * col[k].z;
                r.w = p.w * col[k].w;
                __stcs(reinterpret_cast<float4*>(obase + (size_t)t3 * LPIX), r);
                t3++;
            }
        }
    }
}

extern "C" void kernel_launch(void* const* d_in, const int* in_sizes, int n_in,
                              void* d_out, int out_size)
{
    const float* x = (const float*)d_in[0];
    float* out = (float*)d_out;
    // tpcm2 (d_in[1]) / tpcm3 (d_in[2]) are compile-time constants for K=3; hardcoded.
    (void)in_sizes; (void)n_in; (void)out_size;

    const int total_threads = 4 * 8 * (LPIX / 4);   // 131072
    const int block = 256;
    const int grid = total_threads / block;         // 512
    high_order_kernel<<<grid, block>>>(x, out);
}

// round 2
// speedup vs baseline: 1.1060x; 1.1060x over previous
#include <cuda_runtime.h>
#include <cstdint>

// high_order_input: x[4,8,128,128] f32 -> out[4,8,210,16384] f32
// ht2: 45 pairs col_i*col_j (i<=j); ht3: 165 triples col_i*col_j*col_k (i<=j<=k).
// Enumeration order matches the reference tpcm2/tpcm3 construction (verified R1,
// rel_err 3.9e-08). R2: 2 pixels/thread (float2) to cut regs 64->~40 and raise
// resident warps 32->48/SM; kernel is HBM-write-bound and was concurrency-starved.

#define HWDIM 128
#define LPIX  (HWDIM * HWDIM)   // 16384
#define NTERM 210

__global__ __launch_bounds__(256, 6)
void high_order_kernel(const float* __restrict__ x, float* __restrict__ out)
{
    const int tid = blockIdx.x * blockDim.x + threadIdx.x;
    // 32 planes * 16384 pixels / 2 pixels-per-thread = 262144 threads
    const int plane = tid >> 13;          // tid / 8192
    const int q     = tid & 8191;
    const int h     = q >> 6;             // q / 64
    const int w0    = (q & 63) << 1;      // 2-pixel group start

    const float* __restrict__ xp = x + (size_t)plane * LPIX;

    // 3x3 neighborhood for 2 consecutive pixels: col[kh*3+kw] holds
    // x[h+kh-1][w0+kw-1 .. w0+kw] with zero padding.
    float2 col[9];
    #pragma unroll
    for (int dr = 0; dr < 3; dr++) {
        const int r = h + dr - 1;
        float v0, v3;
        float2 mid;
        if (r < 0 || r >= HWDIM) {
            v0 = 0.f; v3 = 0.f;
            mid = make_float2(0.f, 0.f);
        } else {
            const float* rp = xp + r * HWDIM + w0;
            mid = *reinterpret_cast<const float2*>(rp);          // aligned (w0 % 2 == 0)
            v0 = (w0 > 0)          ? __ldg(rp - 1) : 0.f;
            v3 = (w0 + 2 < HWDIM)  ? __ldg(rp + 2) : 0.f;
        }
        col[dr * 3 + 0] = make_float2(v0,    mid.x);
        col[dr * 3 + 1] = mid;
        col[dr * 3 + 2] = make_float2(mid.y, v3);
    }

    float* __restrict__ obase = out + (size_t)plane * NTERM * LPIX + (size_t)(h * HWDIM + w0);

    // t2 = 0..44 (i-major, j>=i); t3 = 45..209 (i-major, j>=i, k>=j).
    // p_ij is both the ht2 value and the shared prefix of all (i,j,*) triples.
    int t2 = 0;
    int t3 = 45;
    #pragma unroll
    for (int i = 0; i < 9; i++) {
        #pragma unroll
        for (int j = i; j < 9; j++) {
            float2 p;
            p.x = col[i].x * col[j].x;
            p.y = col[i].y * col[j].y;
            __stcs(reinterpret_cast<float2*>(obase + (size_t)t2 * LPIX), p);
            t2++;
            #pragma unroll
            for (int k = j; k < 9; k++) {
                float2 r;
                r.x = p.x * col[k].x;
                r.y = p.y * col[k].y;
                __stcs(reinterpret_cast<float2*>(obase + (size_t)t3 * LPIX), r);
                t3++;
            }
        }
    }
}

extern "C" void kernel_launch(void* const* d_in, const int* in_sizes, int n_in,
                              void* d_out, int out_size)
{
    const float* x = (const float*)d_in[0];
    float* out = (float*)d_out;
    // tpcm2 (d_in[1]) / tpcm3 (d_in[2]) are compile-time constants for K=3; hardcoded.
    (void)in_sizes; (void)n_in; (void)out_size;

    const int total_threads = 4 * 8 * (LPIX / 2);   // 262144
    const int block = 256;
    const int grid = total_threads / block;         // 1024
    high_order_kernel<<<grid, block>>>(x, out);
}